// round 7
// baseline (speedup 1.0000x reference)
#include <cuda_runtime.h>
#include <cuda_bf16.h>
#include <math.h>
#include <stdint.h>

// ---------------------------------------------------------------------------
// Problem constants: x(2,4,1024,1024), HEADS=8, D=128, ROT_DIM=64
// ---------------------------------------------------------------------------
#define BATCH   2
#define CH      4
#define BC      (BATCH*CH)        // 8
#define NB      1024              // BINS
#define NH      8                 // heads
#define HD      128               // head dim
#define BCN     (BC*NH)           // 64
#define ROT     64                // rotary dims

// Scratch (static __device__ — no allocations allowed)
__device__ float g_y [BC  * NB * NB];   // proj gemm out (pre-conv)      32MB
__device__ float g_p [BC  * NB * NB];   // conv+bias out (tf32, also V^T) 32MB
__device__ float g_q [BCN * NB * HD];   // roped Q (= K), tf32            32MB
__device__ float g_s [BCN * NB * NB];   // attention probs, tf32         256MB
__device__ float g_av[BCN * NB * HD];   // softmax @ V                    32MB
__device__ float g_am[BC  * NB * NB];   // merged heads, tf32             32MB
__device__ float g_xc[BC  * NB * NB];   // x converted to tf32            32MB
__device__ float g_wl[CH  * NB * NB];   // w_lin tf32                     16MB
__device__ float g_wo[CH  * NB * NB];   // w_out tf32                     16MB

// ---------------------------------------------------------------------------
// helpers
// ---------------------------------------------------------------------------
__device__ __forceinline__ unsigned f2tf32(float x) {
    unsigned r;
    asm("cvt.rna.tf32.f32 %0, %1;" : "=r"(r) : "f"(x));
    return r;
}
__device__ __forceinline__ float rtf(float x) { return __uint_as_float(f2tf32(x)); }

__device__ __forceinline__ uint32_t smem_u32(const void* p) {
    uint32_t a;
    asm("{ .reg .u64 t; cvta.to.shared.u64 t, %1; cvt.u32.u64 %0, t; }"
        : "=r"(a) : "l"(p));
    return a;
}

__device__ __forceinline__ void cp16(uint32_t dst, const void* src) {
    asm volatile("cp.async.ca.shared.global [%0], [%1], 16;" :: "r"(dst), "l"(src));
}
#define CP_COMMIT() asm volatile("cp.async.commit_group;" ::: "memory")
#define CP_WAIT(n)  asm volatile("cp.async.wait_group %0;" :: "n"(n) : "memory")

__device__ __forceinline__ void mma_tf32(float* d, const unsigned* a, const unsigned* b) {
    asm volatile(
        "mma.sync.aligned.m16n8k8.row.col.f32.tf32.tf32.f32 "
        "{%0,%1,%2,%3}, {%4,%5,%6,%7}, {%8,%9}, {%0,%1,%2,%3};"
        : "+f"(d[0]), "+f"(d[1]), "+f"(d[2]), "+f"(d[3])
        : "r"(a[0]), "r"(a[1]), "r"(a[2]), "r"(a[3]), "r"(b[0]), "r"(b[1]));
}

// ---------------------------------------------------------------------------
// elementwise tf32 rounding pass (for x, w_lin, w_out)
// ---------------------------------------------------------------------------
__global__ __launch_bounds__(256)
void cvt_tf32(const float* __restrict__ in, float* __restrict__ out, int n4)
{
    int i = blockIdx.x * 256 + threadIdx.x;
    if (i >= n4) return;
    float4 v = ((const float4*)in)[i];
    v.x = rtf(v.x); v.y = rtf(v.y); v.z = rtf(v.z); v.w = rtf(v.w);
    ((float4*)out)[i] = v;
}

// ---------------------------------------------------------------------------
// Batched NT GEMM, tensor cores (tf32, fp32 acc), inputs pre-rounded to tf32.
//   C[m,n] = sum_k A[m*lda+k] * B[n*ldb+k]
// 256 threads (8 warps, 2x4), block 128x128, warp tile 64x32 (4x4 m16n8k8).
// BK=32, 3-stage cp.async pipeline, ONE __syncthreads per iteration
// (CUTLASS multistage order: the top-of-iter barrier certifies that every
// warp finished the slot being refilled this iteration).
// Smem rows stride 36 -> frag banks (4g+t+k0)%32 conflict-free.
// __launch_bounds__(256,2): 2 CTAs/SM; smem 2x110.6KB = 221KB fits 228KB.
// B batch pointer = B + (batch % modB) * sB.
// ---------------------------------------------------------------------------
#define STG_F 9216          // floats per stage (2 * 128 * 36)
#define NSTG  3
#define GEMM_SMEM (NSTG * STG_F * 4)   // 110592 B

__device__ __forceinline__ void issue_stage(uint32_t sbase, int slot,
    const float* Ag, const float* Bg, int kbase, int lda, int ldb, int tid)
{
    const int r  = tid >> 1;            // 0..127
    const int c0 = (tid & 1) * 16;      // 0 or 16
    uint32_t a_off = sbase + (uint32_t)(slot * STG_F + r * 36 + c0) * 4u;
    uint32_t b_off = a_off + 4608u * 4u;        // + 128*36 floats
    const float* ap = Ag + (long)r * lda + kbase + c0;
    const float* bp = Bg + (long)r * ldb + kbase + c0;
    #pragma unroll
    for (int i = 0; i < 4; i++) {
        cp16(a_off + i * 16, ap + i * 4);
        cp16(b_off + i * 16, bp + i * 4);
    }
}

__global__ __launch_bounds__(256, 2)
void gemm_tc(const float* __restrict__ A, const float* __restrict__ B,
             float* __restrict__ C,
             int K, int lda, int ldb, int ldc,
             long sA, long sB, long sC, int modB)
{
    extern __shared__ float sm[];
    const uint32_t sbase = smem_u32(sm);

    const int tid = threadIdx.x;
    const int batch = blockIdx.z;
    const int bm = blockIdx.y * 128;
    const int bn = blockIdx.x * 128;

    const float* Ag = A + (long)batch * sA + (long)bm * lda;
    const float* Bg = B + (long)(batch % modB) * sB + (long)bn * ldb;
    C += (long)batch * sC;

    const int wid  = tid >> 5;
    const int lane = tid & 31;
    const int wm = wid & 1;             // 0..1 (64 rows)
    const int wn = wid >> 1;            // 0..3 (32 cols)
    const int g = lane >> 2;            // 0..7
    const int t = lane & 3;             // 0..3

    float acc[4][4][4];
    #pragma unroll
    for (int i = 0; i < 4; i++)
        #pragma unroll
        for (int j = 0; j < 4; j++)
            #pragma unroll
            for (int r = 0; r < 4; r++) acc[i][j][r] = 0.f;

    const int iters = K >> 5;           // BK = 32

    // prologue: stages 0,1
    issue_stage(sbase, 0, Ag, Bg, 0, lda, ldb, tid);
    CP_COMMIT();
    if (1 < iters) issue_stage(sbase, 1, Ag, Bg, 32, lda, ldb, tid);
    CP_COMMIT();

    int slot = 0;                       // = it % 3
    for (int it = 0; it < iters; ++it) {
        CP_WAIT(1);                     // stage `it` complete
        __syncthreads();                // also certifies slot (it-1)%3 consumed

        // refill the slot freed last iteration (safe after the barrier)
        if (it + 2 < iters) {
            int ns = slot + 2; if (ns >= 3) ns -= 3;
            issue_stage(sbase, ns, Ag, Bg, (it + 2) * 32, lda, ldb, tid);
        }
        CP_COMMIT();                    // unconditional: group idx == stage idx

        const float* sA = sm + slot * STG_F;         // [128][36]
        const float* sB = sA + 4608;                 // [128][36]

        #pragma unroll
        for (int ks = 0; ks < 4; ++ks) {
            const int k0 = ks * 8;
            unsigned af[4][4], bf[4][2];
            #pragma unroll
            for (int mt = 0; mt < 4; mt++) {
                const int m = wm * 64 + mt * 16 + g;
                af[mt][0] = __float_as_uint(sA[m * 36 + k0 + t]);
                af[mt][1] = __float_as_uint(sA[(m + 8) * 36 + k0 + t]);
                af[mt][2] = __float_as_uint(sA[m * 36 + k0 + t + 4]);
                af[mt][3] = __float_as_uint(sA[(m + 8) * 36 + k0 + t + 4]);
            }
            #pragma unroll
            for (int nt = 0; nt < 4; nt++) {
                const int n = wn * 32 + nt * 8 + g;
                bf[nt][0] = __float_as_uint(sB[n * 36 + k0 + t]);
                bf[nt][1] = __float_as_uint(sB[n * 36 + k0 + t + 4]);
            }
            #pragma unroll
            for (int mt = 0; mt < 4; mt++)
                #pragma unroll
                for (int nt = 0; nt < 4; nt++)
                    mma_tf32(acc[mt][nt], af[mt], bf[nt]);
        }
        slot++; if (slot >= 3) slot = 0;
    }

    // epilogue
    #pragma unroll
    for (int mt = 0; mt < 4; mt++) {
        const int row = bm + wm * 64 + mt * 16 + g;
        #pragma unroll
        for (int nt = 0; nt < 4; nt++) {
            const int col = bn + wn * 32 + nt * 8 + 2 * t;
            float2 v0 = make_float2(acc[mt][nt][0], acc[mt][nt][1]);
            float2 v1 = make_float2(acc[mt][nt][2], acc[mt][nt][3]);
            *(float2*)(C + (long)row * ldc + col)       = v0;
            *(float2*)(C + (long)(row + 8) * ldc + col) = v1;
        }
    }
}

// ---------------------------------------------------------------------------
// Depthwise conv (kernel 3, pad 1 along last axis) + bias; output tf32-rounded
// ---------------------------------------------------------------------------
__global__ __launch_bounds__(256)
void conv_bias(const float* __restrict__ y, const float* __restrict__ wc,
               const float* __restrict__ bias, float* __restrict__ p)
{
    long idx = (long)blockIdx.x * blockDim.x + threadIdx.x;   // 8M elems
    if (idx >= (long)BC * NB * NB) return;
    int o = (int)(idx & (NB - 1));
    int c = (int)((idx >> 20) & 3);
    float w0 = wc[c*3+0], w1 = wc[c*3+1], w2 = wc[c*3+2];
    float mid = y[idx];
    float lft = (o > 0)      ? y[idx - 1] : 0.f;
    float rgt = (o < NB - 1) ? y[idx + 1] : 0.f;
    p[idx] = rtf(fmaf(lft, w0, fmaf(mid, w1, fmaf(rgt, w2, bias[c]))));
}

// ---------------------------------------------------------------------------
// RoPE + transpose: Q[bcn][s][d] from p[bc][n*128+d][s]; output tf32-rounded
// ---------------------------------------------------------------------------
__global__ __launch_bounds__(256)
void rope_build(const float* __restrict__ p, float* __restrict__ Q)
{
    long idx = (long)blockIdx.x * blockDim.x + threadIdx.x;   // 4M
    if (idx >= (long)BCN * 64 * NB) return;
    int s   = (int)(idx & (NB - 1));
    int j   = (int)((idx >> 10) & 63);
    int bcn = (int)(idx >> 16);
    int bc = bcn >> 3, n = bcn & 7;

    const float* src = p + ((long)bc * NB + n * HD) * NB + s;
    float*       dst = Q + (long)bcn * (NB * HD) + (long)s * HD;

    if (j < 32) {
        float t0 = src[(2*j + 0) * NB];
        float t1 = src[(2*j + 1) * NB];
        float invf = powf(10000.f, -(float)(2*j) / (float)ROT);
        float ang = (float)s * invf;
        float cs = cosf(ang), sn = sinf(ang);
        dst[2*j + 0] = rtf(t0 * cs - t1 * sn);
        dst[2*j + 1] = rtf(t1 * cs + t0 * sn);
    } else {
        int d = ROT + (j - 32) * 2;
        dst[d + 0] = src[(d + 0) * NB];
        dst[d + 1] = src[(d + 1) * NB];
    }
}

// ---------------------------------------------------------------------------
// Row softmax with scale (one block per row of 1024); output tf32-rounded
// ---------------------------------------------------------------------------
__global__ __launch_bounds__(256)
void softmax_rows(float* __restrict__ S, float scale)
{
    float* row = S + (long)blockIdx.x * NB;
    const int t = threadIdx.x;
    __shared__ float red[32];

    float v[4];
    float m = -1e30f;
    #pragma unroll
    for (int i = 0; i < 4; i++) {
        v[i] = row[t + i * 256] * scale;
        m = fmaxf(m, v[i]);
    }
    #pragma unroll
    for (int o = 16; o > 0; o >>= 1) m = fmaxf(m, __shfl_xor_sync(~0u, m, o));
    if ((t & 31) == 0) red[t >> 5] = m;
    __syncthreads();
    if (t < 32) {
        float x = red[t & 7];
        #pragma unroll
        for (int o = 4; o > 0; o >>= 1) x = fmaxf(x, __shfl_xor_sync(~0u, x, o));
        red[t] = x;
    }
    __syncthreads();
    m = red[0];

    float sum = 0.f;
    #pragma unroll
    for (int i = 0; i < 4; i++) { v[i] = __expf(v[i] - m); sum += v[i]; }
    #pragma unroll
    for (int o = 16; o > 0; o >>= 1) sum += __shfl_xor_sync(~0u, sum, o);
    __syncthreads();
    if ((t & 31) == 0) red[t >> 5] = sum;
    __syncthreads();
    if (t < 32) {
        float x = red[t & 7];
        #pragma unroll
        for (int o = 4; o > 0; o >>= 1) x += __shfl_xor_sync(~0u, x, o);
        red[t] = x;
    }
    __syncthreads();
    float inv = 1.f / red[0];
    #pragma unroll
    for (int i = 0; i < 4; i++) row[t + i * 256] = rtf(v[i] * inv);
}

// ---------------------------------------------------------------------------
// Merge heads: a_m[bc][n*128+d][s] = av[bcn][s][d]; output tf32-rounded
// ---------------------------------------------------------------------------
__global__ __launch_bounds__(256)
void merge_heads(const float* __restrict__ av, float* __restrict__ am)
{
    __shared__ float tile[32][33];
    int bcn = blockIdx.z;
    const float* src = av + (long)bcn * (NB * HD);
    float*       dst = am + (long)bcn * (NB * HD);
    int d0 = blockIdx.x * 32, s0 = blockIdx.y * 32;
    int tx = threadIdx.x, ty = threadIdx.y;
    #pragma unroll
    for (int i = 0; i < 32; i += 8)
        tile[ty + i][tx] = src[(long)(s0 + ty + i) * HD + d0 + tx];
    __syncthreads();
    #pragma unroll
    for (int i = 0; i < 32; i += 8)
        dst[(long)(d0 + ty + i) * NB + s0 + tx] = rtf(tile[tx][ty + i]);
}

// ---------------------------------------------------------------------------
// Launch
// ---------------------------------------------------------------------------
extern "C" void kernel_launch(void* const* d_in, const int* in_sizes, int n_in,
                              void* d_out, int out_size)
{
    const float* x      = (const float*)d_in[0];  // (2,4,1024,1024)
    const float* w_lin  = (const float*)d_in[1];  // (4,1024,1024)
    const float* w_conv = (const float*)d_in[2];  // (4,1,1,3)
    const float* b_conv = (const float*)d_in[3];  // (4,)
    const float* w_out  = (const float*)d_in[4];  // (4,1024,1024)
    float* out = (float*)d_out;

    float *y, *p, *q, *s, *av, *am, *xc, *wl, *wo;
    cudaGetSymbolAddress((void**)&y,  g_y);
    cudaGetSymbolAddress((void**)&p,  g_p);
    cudaGetSymbolAddress((void**)&q,  g_q);
    cudaGetSymbolAddress((void**)&s,  g_s);
    cudaGetSymbolAddress((void**)&av, g_av);
    cudaGetSymbolAddress((void**)&am, g_am);
    cudaGetSymbolAddress((void**)&xc, g_xc);
    cudaGetSymbolAddress((void**)&wl, g_wl);
    cudaGetSymbolAddress((void**)&wo, g_wo);

    cudaFuncSetAttribute(gemm_tc, cudaFuncAttributeMaxDynamicSharedMemorySize, GEMM_SMEM);

    const long MM = (long)NB * NB;          // 1048576
    const long QS = (long)NB * HD;          // 131072

    // 0) pre-round GEMM inputs to tf32
    cvt_tf32<<<(int)(BC * MM / 4 / 256), 256>>>(x, xc, (int)(BC * MM / 4));
    cvt_tf32<<<(int)(CH * MM / 4 / 256), 256>>>(w_lin, wl, (int)(CH * MM / 4));
    cvt_tf32<<<(int)(CH * MM / 4 / 256), 256>>>(w_out, wo, (int)(CH * MM / 4));

    // 1) proj GEMM: y[bc] = x[bc] @ w_lin[c]^T
    gemm_tc<<<dim3(8, 8, BC), 256, GEMM_SMEM>>>(xc, wl, y,
        NB, NB, NB, NB, MM, MM, MM, CH);

    // 2) depthwise conv3 + bias (writes tf32 p)
    conv_bias<<<(int)((BC * MM + 255) / 256), 256>>>(y, w_conv, b_conv, p);

    // 3) RoPE -> Q (== K), tf32
    rope_build<<<(int)(((long)BCN * 64 * NB + 255) / 256), 256>>>(p, q);

    // 4) scores = Q @ Q^T  (scale folded into softmax)
    gemm_tc<<<dim3(8, 8, BCN), 256, GEMM_SMEM>>>(q, q, s,
        HD, HD, HD, NB, QS, QS, MM, BCN);

    // 5) softmax rows, scale = 1/sqrt(1024), writes tf32 probs
    softmax_rows<<<BCN * NB, 256>>>(s, 1.0f / 32.0f);

    // 6) av = P @ V   (V^T is the p slice: stride 131072 per bcn, ldb=1024)
    gemm_tc<<<dim3(1, 8, BCN), 256, GEMM_SMEM>>>(s, p, av,
        NB, NB, NB, HD, MM, QS, QS, BCN);

    // 7) merge heads (batched transpose), writes tf32 am
    merge_heads<<<dim3(4, 32, BCN), dim3(32, 8)>>>(av, am);

    // 8) out GEMM: out[bc] = am[bc] @ w_out[c]^T
    gemm_tc<<<dim3(8, 8, BC), 256, GEMM_SMEM>>>(am, wo, out,
        NB, NB, NB, NB, MM, MM, MM, CH);
}

// round 10
// speedup vs baseline: 1.2443x; 1.2443x over previous
#include <cuda_runtime.h>
#include <cuda_bf16.h>
#include <math.h>
#include <stdint.h>

// ---------------------------------------------------------------------------
// Problem constants: x(2,4,1024,1024), HEADS=8, D=128, ROT_DIM=64
// ---------------------------------------------------------------------------
#define BATCH   2
#define CH      4
#define BC      (BATCH*CH)        // 8
#define NB      1024              // BINS
#define NH      8                 // heads
#define HD      128               // head dim
#define BCN     (BC*NH)           // 64
#define ROT     64                // rotary dims

// Scratch (static __device__ — no allocations allowed)
__device__ float g_y [BC  * NB * NB];   // proj gemm out (pre-conv)      32MB
__device__ float g_p [BC  * NB * NB];   // conv+bias out (tf32, also V^T) 32MB
__device__ float g_q [BCN * NB * HD];   // roped Q (= K), tf32            32MB
__device__ float g_s [BCN * NB * NB];   // attention probs, tf32         256MB
__device__ float g_av[BCN * NB * HD];   // softmax @ V                    32MB
__device__ float g_am[BC  * NB * NB];   // merged heads, tf32             32MB
__device__ float g_xc[BC  * NB * NB];   // x converted to tf32            32MB
__device__ float g_wl[CH  * NB * NB];   // w_lin tf32                     16MB
__device__ float g_wo[CH  * NB * NB];   // w_out tf32                     16MB

// ---------------------------------------------------------------------------
// helpers
// ---------------------------------------------------------------------------
__device__ __forceinline__ unsigned f2tf32(float x) {
    unsigned r;
    asm("cvt.rna.tf32.f32 %0, %1;" : "=r"(r) : "f"(x));
    return r;
}
__device__ __forceinline__ float rtf(float x) { return __uint_as_float(f2tf32(x)); }

__device__ __forceinline__ uint32_t smem_u32(const void* p) {
    uint32_t a;
    asm("{ .reg .u64 t; cvta.to.shared.u64 t, %1; cvt.u32.u64 %0, t; }"
        : "=r"(a) : "l"(p));
    return a;
}

__device__ __forceinline__ void cp16(uint32_t dst, const void* src) {
    asm volatile("cp.async.ca.shared.global [%0], [%1], 16;" :: "r"(dst), "l"(src));
}

// cp.async arrive-on-mbarrier, NOINC: this thread's prior cp.asyncs count ONE
// arrival against the INIT count (the plain form is inc-then-arrive == no-op
// vs the expected count -> deadlock; that was the round-8/9 hang).
__device__ __forceinline__ void cp_arrive(uint32_t mbar) {
    asm volatile("cp.async.mbarrier.arrive.noinc.shared.b64 [%0];" :: "r"(mbar) : "memory");
}

#define MBAR_INIT(addr, cnt) \
    asm volatile("mbarrier.init.shared.b64 [%0], %1;" :: "r"(addr), "r"(cnt) : "memory")

__device__ __forceinline__ void mbar_arrive(uint32_t addr) {
    asm volatile("mbarrier.arrive.shared.b64 _, [%0];" :: "r"(addr) : "memory");
}

__device__ __forceinline__ void mbar_wait(uint32_t addr, uint32_t parity) {
    asm volatile(
        "{\n\t.reg .pred P1;\n\t"
        "WL_%=:\n\t"
        "mbarrier.try_wait.parity.acquire.cta.shared::cta.b64 P1, [%0], %1, 0x989680;\n\t"
        "@P1 bra.uni WD_%=;\n\t"
        "bra.uni WL_%=;\n\t"
        "WD_%=:\n\t}"
        :: "r"(addr), "r"(parity) : "memory");
}

__device__ __forceinline__ void mma_tf32(float* d, const unsigned* a, const unsigned* b) {
    asm volatile(
        "mma.sync.aligned.m16n8k8.row.col.f32.tf32.tf32.f32 "
        "{%0,%1,%2,%3}, {%4,%5,%6,%7}, {%8,%9}, {%0,%1,%2,%3};"
        : "+f"(d[0]), "+f"(d[1]), "+f"(d[2]), "+f"(d[3])
        : "r"(a[0]), "r"(a[1]), "r"(a[2]), "r"(a[3]), "r"(b[0]), "r"(b[1]));
}

// ---------------------------------------------------------------------------
// elementwise tf32 rounding pass (for x, w_lin, w_out)
// ---------------------------------------------------------------------------
__global__ __launch_bounds__(256)
void cvt_tf32(const float* __restrict__ in, float* __restrict__ out, int n4)
{
    int i = blockIdx.x * 256 + threadIdx.x;
    if (i >= n4) return;
    float4 v = ((const float4*)in)[i];
    v.x = rtf(v.x); v.y = rtf(v.y); v.z = rtf(v.z); v.w = rtf(v.w);
    ((float4*)out)[i] = v;
}

// ---------------------------------------------------------------------------
// Batched NT GEMM, tensor cores (tf32, fp32 acc), inputs pre-rounded to tf32.
//   C[m,n] = sum_k A[m*lda+k] * B[n*ldb+k]
// 256 threads (8 warps, 2x4), block 128x128, warp tile 64x32 (4x4 m16n8k8).
// BK=16, 4 smem slots. NO __syncthreads in the k-loop: per-stage mbarrier
// pipeline. full[s]: 256 cp.async-noinc arrivals. empty[s]: 8 warp arrivals
// (lane 0 per warp; valid because mma.sync keeps the warp converged, so
// lane 0 reaching the release point implies all lanes' LDS are done).
// Warps skew freely up to 3 stages -> LDS/MMA/cp.async overlap across warps.
// Smem rows stride 20 -> frag loads conflict-free.
// __launch_bounds__(256,2): 2 CTAs/SM. smem/CTA = 64B + 80KB.
// B batch pointer = B + (batch % modB) * sB.
// ---------------------------------------------------------------------------
#define STG_F 5120          // floats per stage (2*128*20)
#define NSTG  4
#define GEMM_SMEM (64 + NSTG * STG_F * 4)   // 64B barriers + 80KB stages

__device__ __forceinline__ void issue_stage(uint32_t dbase, int slot,
    const float* Ag, const float* Bg, int kbase, int lda, int ldb, int tid)
{
    const int r  = tid >> 1;            // 0..127
    const int c0 = (tid & 1) * 8;       // 0 or 8
    uint32_t a_off = dbase + (uint32_t)(slot * STG_F + r * 20 + c0) * 4u;
    uint32_t b_off = a_off + 2560u * 4u;
    const float* ap = Ag + (long)r * lda + kbase + c0;
    const float* bp = Bg + (long)r * ldb + kbase + c0;
    cp16(a_off,      ap);
    cp16(a_off + 16, ap + 4);
    cp16(b_off,      bp);
    cp16(b_off + 16, bp + 4);
}

__global__ __launch_bounds__(256, 2)
void gemm_tc(const float* __restrict__ A, const float* __restrict__ B,
             float* __restrict__ C,
             int K, int lda, int ldb, int ldc,
             long sA, long sB, long sC, int modB)
{
    extern __shared__ float sm[];
    const uint32_t sbase = smem_u32(sm);     // barriers: full[4] @0, empty[4] @32
    const uint32_t dbase = sbase + 64;       // stage data
    float* stg = sm + 16;                    // same region as dbase (float idx)

    const int tid = threadIdx.x;
    const int batch = blockIdx.z;
    const int bm = blockIdx.y * 128;
    const int bn = blockIdx.x * 128;

    const float* Ag = A + (long)batch * sA + (long)bm * lda;
    const float* Bg = B + (long)(batch % modB) * sB + (long)bn * ldb;
    C += (long)batch * sC;

    const int wid  = tid >> 5;
    const int lane = tid & 31;
    const int wm = wid & 1;             // 0..1 (64 rows)
    const int wn = wid >> 1;            // 0..3 (32 cols)
    const int g = lane >> 2;            // 0..7
    const int t = lane & 3;             // 0..3

    float acc[4][4][4];
    #pragma unroll
    for (int i = 0; i < 4; i++)
        #pragma unroll
        for (int j = 0; j < 4; j++)
            #pragma unroll
            for (int r = 0; r < 4; r++) acc[i][j][r] = 0.f;

    const int iters = K >> 4;           // BK = 16

    // init barriers, then CTA-wide sync once
    if (tid < NSTG) {
        MBAR_INIT(sbase + tid * 8, 256);        // full[tid]: all threads' cp.asyncs
        MBAR_INIT(sbase + 32 + tid * 8, 8);     // empty[tid]: one arrive per warp
    }
    __syncthreads();

    // prefill stages 0..2 (first use of slots 0..2: no empty wait)
    #pragma unroll
    for (int s = 0; s < 3; s++) {
        issue_stage(dbase, s, Ag, Bg, s * 16, lda, ldb, tid);
        cp_arrive(sbase + s * 8);
    }

    for (int it = 0; it < iters; ++it) {
        // 1) produce stage it+3
        const int pn = it + 3;
        if (pn < iters) {
            const int ps = pn & 3;
            if (pn >= NSTG)  // slot reuse: wait for all warps to release it
                mbar_wait(sbase + 32 + ps * 8, ((pn >> 2) - 1) & 1);
            issue_stage(dbase, ps, Ag, Bg, pn * 16, lda, ldb, tid);
            cp_arrive(sbase + ps * 8);
        }

        // 2) wait for stage it
        const int slot = it & 3;
        mbar_wait(sbase + slot * 8, (it >> 2) & 1);

        const float* tA = stg + slot * STG_F;        // [128][20]
        const float* tB = tA + 2560;                 // [128][20]

        // 3) compute
        #pragma unroll
        for (int ks = 0; ks < 2; ++ks) {
            const int k0 = ks * 8;
            unsigned af[4][4], bf[4][2];
            #pragma unroll
            for (int mt = 0; mt < 4; mt++) {
                const int m = wm * 64 + mt * 16 + g;
                af[mt][0] = __float_as_uint(tA[m * 20 + k0 + t]);
                af[mt][1] = __float_as_uint(tA[(m + 8) * 20 + k0 + t]);
                af[mt][2] = __float_as_uint(tA[m * 20 + k0 + t + 4]);
                af[mt][3] = __float_as_uint(tA[(m + 8) * 20 + k0 + t + 4]);
            }
            #pragma unroll
            for (int nt = 0; nt < 4; nt++) {
                const int n = wn * 32 + nt * 8 + g;
                bf[nt][0] = __float_as_uint(tB[n * 20 + k0 + t]);
                bf[nt][1] = __float_as_uint(tB[n * 20 + k0 + t + 4]);
            }
            #pragma unroll
            for (int mt = 0; mt < 4; mt++)
                #pragma unroll
                for (int nt = 0; nt < 4; nt++)
                    mma_tf32(acc[mt][nt], af[mt], bf[nt]);
        }

        // 4) stage consumed -> warp-level release (lane 0; warp is converged)
        if (lane == 0) mbar_arrive(sbase + 32 + slot * 8);
    }

    // epilogue
    #pragma unroll
    for (int mt = 0; mt < 4; mt++) {
        const int row = bm + wm * 64 + mt * 16 + g;
        #pragma unroll
        for (int nt = 0; nt < 4; nt++) {
            const int col = bn + wn * 32 + nt * 8 + 2 * t;
            float2 v0 = make_float2(acc[mt][nt][0], acc[mt][nt][1]);
            float2 v1 = make_float2(acc[mt][nt][2], acc[mt][nt][3]);
            *(float2*)(C + (long)row * ldc + col)       = v0;
            *(float2*)(C + (long)(row + 8) * ldc + col) = v1;
        }
    }
}

// ---------------------------------------------------------------------------
// Depthwise conv (kernel 3, pad 1 along last axis) + bias; output tf32-rounded
// ---------------------------------------------------------------------------
__global__ __launch_bounds__(256)
void conv_bias(const float* __restrict__ y, const float* __restrict__ wc,
               const float* __restrict__ bias, float* __restrict__ p)
{
    long idx = (long)blockIdx.x * blockDim.x + threadIdx.x;   // 8M elems
    if (idx >= (long)BC * NB * NB) return;
    int o = (int)(idx & (NB - 1));
    int c = (int)((idx >> 20) & 3);
    float w0 = wc[c*3+0], w1 = wc[c*3+1], w2 = wc[c*3+2];
    float mid = y[idx];
    float lft = (o > 0)      ? y[idx - 1] : 0.f;
    float rgt = (o < NB - 1) ? y[idx + 1] : 0.f;
    p[idx] = rtf(fmaf(lft, w0, fmaf(mid, w1, fmaf(rgt, w2, bias[c]))));
}

// ---------------------------------------------------------------------------
// RoPE + transpose: Q[bcn][s][d] from p[bc][n*128+d][s]; output tf32-rounded
// ---------------------------------------------------------------------------
__global__ __launch_bounds__(256)
void rope_build(const float* __restrict__ p, float* __restrict__ Q)
{
    long idx = (long)blockIdx.x * blockDim.x + threadIdx.x;   // 4M
    if (idx >= (long)BCN * 64 * NB) return;
    int s   = (int)(idx & (NB - 1));
    int j   = (int)((idx >> 10) & 63);
    int bcn = (int)(idx >> 16);
    int bc = bcn >> 3, n = bcn & 7;

    const float* src = p + ((long)bc * NB + n * HD) * NB + s;
    float*       dst = Q + (long)bcn * (NB * HD) + (long)s * HD;

    if (j < 32) {
        float t0 = src[(2*j + 0) * NB];
        float t1 = src[(2*j + 1) * NB];
        float invf = powf(10000.f, -(float)(2*j) / (float)ROT);
        float ang = (float)s * invf;
        float cs = cosf(ang), sn = sinf(ang);
        dst[2*j + 0] = rtf(t0 * cs - t1 * sn);
        dst[2*j + 1] = rtf(t1 * cs + t0 * sn);
    } else {
        int d = ROT + (j - 32) * 2;
        dst[d + 0] = src[(d + 0) * NB];
        dst[d + 1] = src[(d + 1) * NB];
    }
}

// ---------------------------------------------------------------------------
// Row softmax with scale (one block per row of 1024); output tf32-rounded
// ---------------------------------------------------------------------------
__global__ __launch_bounds__(256)
void softmax_rows(float* __restrict__ S, float scale)
{
    float* row = S + (long)blockIdx.x * NB;
    const int t = threadIdx.x;
    __shared__ float red[32];

    float v[4];
    float m = -1e30f;
    #pragma unroll
    for (int i = 0; i < 4; i++) {
        v[i] = row[t + i * 256] * scale;
        m = fmaxf(m, v[i]);
    }
    #pragma unroll
    for (int o = 16; o > 0; o >>= 1) m = fmaxf(m, __shfl_xor_sync(~0u, m, o));
    if ((t & 31) == 0) red[t >> 5] = m;
    __syncthreads();
    if (t < 32) {
        float x = red[t & 7];
        #pragma unroll
        for (int o = 4; o > 0; o >>= 1) x = fmaxf(x, __shfl_xor_sync(~0u, x, o));
        red[t] = x;
    }
    __syncthreads();
    m = red[0];

    float sum = 0.f;
    #pragma unroll
    for (int i = 0; i < 4; i++) { v[i] = __expf(v[i] - m); sum += v[i]; }
    #pragma unroll
    for (int o = 16; o > 0; o >>= 1) sum += __shfl_xor_sync(~0u, sum, o);
    __syncthreads();
    if ((t & 31) == 0) red[t >> 5] = sum;
    __syncthreads();
    if (t < 32) {
        float x = red[t & 7];
        #pragma unroll
        for (int o = 4; o > 0; o >>= 1) x += __shfl_xor_sync(~0u, x, o);
        red[t] = x;
    }
    __syncthreads();
    float inv = 1.f / red[0];
    #pragma unroll
    for (int i = 0; i < 4; i++) row[t + i * 256] = rtf(v[i] * inv);
}

// ---------------------------------------------------------------------------
// Merge heads: a_m[bc][n*128+d][s] = av[bcn][s][d]; output tf32-rounded
// ---------------------------------------------------------------------------
__global__ __launch_bounds__(256)
void merge_heads(const float* __restrict__ av, float* __restrict__ am)
{
    __shared__ float tile[32][33];
    int bcn = blockIdx.z;
    const float* src = av + (long)bcn * (NB * HD);
    float*       dst = am + (long)bcn * (NB * HD);
    int d0 = blockIdx.x * 32, s0 = blockIdx.y * 32;
    int tx = threadIdx.x, ty = threadIdx.y;
    #pragma unroll
    for (int i = 0; i < 32; i += 8)
        tile[ty + i][tx] = src[(long)(s0 + ty + i) * HD + d0 + tx];
    __syncthreads();
    #pragma unroll
    for (int i = 0; i < 32; i += 8)
        dst[(long)(d0 + ty + i) * NB + s0 + tx] = rtf(tile[tx][ty + i]);
}

// ---------------------------------------------------------------------------
// Launch
// ---------------------------------------------------------------------------
extern "C" void kernel_launch(void* const* d_in, const int* in_sizes, int n_in,
                              void* d_out, int out_size)
{
    const float* x      = (const float*)d_in[0];  // (2,4,1024,1024)
    const float* w_lin  = (const float*)d_in[1];  // (4,1024,1024)
    const float* w_conv = (const float*)d_in[2];  // (4,1,1,3)
    const float* b_conv = (const float*)d_in[3];  // (4,)
    const float* w_out  = (const float*)d_in[4];  // (4,1024,1024)
    float* out = (float*)d_out;

    float *y, *p, *q, *s, *av, *am, *xc, *wl, *wo;
    cudaGetSymbolAddress((void**)&y,  g_y);
    cudaGetSymbolAddress((void**)&p,  g_p);
    cudaGetSymbolAddress((void**)&q,  g_q);
    cudaGetSymbolAddress((void**)&s,  g_s);
    cudaGetSymbolAddress((void**)&av, g_av);
    cudaGetSymbolAddress((void**)&am, g_am);
    cudaGetSymbolAddress((void**)&xc, g_xc);
    cudaGetSymbolAddress((void**)&wl, g_wl);
    cudaGetSymbolAddress((void**)&wo, g_wo);

    cudaFuncSetAttribute(gemm_tc, cudaFuncAttributeMaxDynamicSharedMemorySize, GEMM_SMEM);

    const long MM = (long)NB * NB;          // 1048576
    const long QS = (long)NB * HD;          // 131072

    // 0) pre-round GEMM inputs to tf32
    cvt_tf32<<<(int)(BC * MM / 4 / 256), 256>>>(x, xc, (int)(BC * MM / 4));
    cvt_tf32<<<(int)(CH * MM / 4 / 256), 256>>>(w_lin, wl, (int)(CH * MM / 4));
    cvt_tf32<<<(int)(CH * MM / 4 / 256), 256>>>(w_out, wo, (int)(CH * MM / 4));

    // 1) proj GEMM: y[bc] = x[bc] @ w_lin[c]^T
    gemm_tc<<<dim3(8, 8, BC), 256, GEMM_SMEM>>>(xc, wl, y,
        NB, NB, NB, NB, MM, MM, MM, CH);

    // 2) depthwise conv3 + bias (writes tf32 p)
    conv_bias<<<(int)((BC * MM + 255) / 256), 256>>>(y, w_conv, b_conv, p);

    // 3) RoPE -> Q (== K), tf32
    rope_build<<<(int)(((long)BCN * 64 * NB + 255) / 256), 256>>>(p, q);

    // 4) scores = Q @ Q^T  (scale folded into softmax)
    gemm_tc<<<dim3(8, 8, BCN), 256, GEMM_SMEM>>>(q, q, s,
        HD, HD, HD, NB, QS, QS, MM, BCN);

    // 5) softmax rows, scale = 1/sqrt(1024), writes tf32 probs
    softmax_rows<<<BCN * NB, 256>>>(s, 1.0f / 32.0f);

    // 6) av = P @ V   (V^T is the p slice: stride 131072 per bcn, ldb=1024)
    gemm_tc<<<dim3(1, 8, BCN), 256, GEMM_SMEM>>>(s, p, av,
        NB, NB, NB, HD, MM, QS, QS, BCN);

    // 7) merge heads (batched transpose), writes tf32 am
    merge_heads<<<dim3(4, 32, BCN), dim3(32, 8)>>>(av, am);

    // 8) out GEMM: out[bc] = am[bc] @ w_out[c]^T
    gemm_tc<<<dim3(8, 8, BC), 256, GEMM_SMEM>>>(am, wo, out,
        NB, NB, NB, NB, MM, MM, MM, CH);
}

// round 11
// speedup vs baseline: 1.4815x; 1.1906x over previous
#include <cuda_runtime.h>
#include <cuda_bf16.h>
#include <math.h>
#include <stdint.h>

// ---------------------------------------------------------------------------
// Problem constants: x(2,4,1024,1024), HEADS=8, D=128, ROT_DIM=64
// ---------------------------------------------------------------------------
#define BATCH   2
#define CH      4
#define BC      (BATCH*CH)        // 8
#define NB      1024              // BINS
#define NH      8                 // heads
#define HD      128               // head dim
#define BCN     (BC*NH)           // 64
#define ROT     64                // rotary dims

// Scratch (static __device__ — no allocations allowed)
__device__ float g_y [BC  * NB * NB];   // proj gemm out (pre-conv)      32MB
__device__ float g_p [BC  * NB * NB];   // conv+bias out (tf32, also V^T) 32MB
__device__ float g_q [BCN * NB * HD];   // roped Q (= K), tf32            32MB
__device__ float g_s [BCN * NB * NB];   // attention probs, tf32         256MB
__device__ float g_av[BCN * NB * HD];   // softmax @ V                    32MB
__device__ float g_am[BC  * NB * NB];   // merged heads, tf32             32MB
__device__ float g_xc[BC  * NB * NB];   // x converted to tf32            32MB
__device__ float g_wl[CH  * NB * NB];   // w_lin tf32                     16MB
__device__ float g_wo[CH  * NB * NB];   // w_out tf32                     16MB

// ---------------------------------------------------------------------------
// helpers
// ---------------------------------------------------------------------------
__device__ __forceinline__ unsigned f2tf32(float x) {
    unsigned r;
    asm("cvt.rna.tf32.f32 %0, %1;" : "=r"(r) : "f"(x));
    return r;
}
__device__ __forceinline__ float rtf(float x) { return __uint_as_float(f2tf32(x)); }

__device__ __forceinline__ uint32_t smem_u32(const void* p) {
    uint32_t a;
    asm("{ .reg .u64 t; cvta.to.shared.u64 t, %1; cvt.u32.u64 %0, t; }"
        : "=r"(a) : "l"(p));
    return a;
}

__device__ __forceinline__ void cp16(uint32_t dst, const void* src) {
    asm volatile("cp.async.ca.shared.global [%0], [%1], 16;" :: "r"(dst), "l"(src));
}

// cp.async arrive-on-mbarrier, NOINC (plain form is inc-then-arrive -> deadlock)
__device__ __forceinline__ void cp_arrive(uint32_t mbar) {
    asm volatile("cp.async.mbarrier.arrive.noinc.shared.b64 [%0];" :: "r"(mbar) : "memory");
}

#define MBAR_INIT(addr, cnt) \
    asm volatile("mbarrier.init.shared.b64 [%0], %1;" :: "r"(addr), "r"(cnt) : "memory")

__device__ __forceinline__ void mbar_arrive(uint32_t addr) {
    asm volatile("mbarrier.arrive.shared.b64 _, [%0];" :: "r"(addr) : "memory");
}

__device__ __forceinline__ void mbar_wait(uint32_t addr, uint32_t parity) {
    asm volatile(
        "{\n\t.reg .pred P1;\n\t"
        "WL_%=:\n\t"
        "mbarrier.try_wait.parity.acquire.cta.shared::cta.b64 P1, [%0], %1, 0x989680;\n\t"
        "@P1 bra.uni WD_%=;\n\t"
        "bra.uni WL_%=;\n\t"
        "WD_%=:\n\t}"
        :: "r"(addr), "r"(parity) : "memory");
}

// ldmatrix x4: 4 m8n8 b16 tiles; per-lane row address. tf32 (32-bit) data:
// an 8x8 b16 tile == 8 rows x 4 fp32 cols; lane i receives fp32 element
// [i/4][i%4] -> exactly the m16n8k8 tf32 mma fragment layout.
__device__ __forceinline__ void ldsm4(unsigned& r0, unsigned& r1, unsigned& r2,
                                      unsigned& r3, uint32_t addr) {
    asm volatile("ldmatrix.sync.aligned.m8n8.x4.shared.b16 {%0,%1,%2,%3}, [%4];"
                 : "=r"(r0), "=r"(r1), "=r"(r2), "=r"(r3) : "r"(addr));
}

__device__ __forceinline__ void mma_tf32(float* d, const unsigned* a, const unsigned* b) {
    asm volatile(
        "mma.sync.aligned.m16n8k8.row.col.f32.tf32.tf32.f32 "
        "{%0,%1,%2,%3}, {%4,%5,%6,%7}, {%8,%9}, {%0,%1,%2,%3};"
        : "+f"(d[0]), "+f"(d[1]), "+f"(d[2]), "+f"(d[3])
        : "r"(a[0]), "r"(a[1]), "r"(a[2]), "r"(a[3]), "r"(b[0]), "r"(b[1]));
}

// ---------------------------------------------------------------------------
// elementwise tf32 rounding pass (for x, w_lin, w_out)
// ---------------------------------------------------------------------------
__global__ __launch_bounds__(256)
void cvt_tf32(const float* __restrict__ in, float* __restrict__ out, int n4)
{
    int i = blockIdx.x * 256 + threadIdx.x;
    if (i >= n4) return;
    float4 v = ((const float4*)in)[i];
    v.x = rtf(v.x); v.y = rtf(v.y); v.z = rtf(v.z); v.w = rtf(v.w);
    ((float4*)out)[i] = v;
}

// ---------------------------------------------------------------------------
// Batched NT GEMM, tensor cores (tf32, fp32 acc), inputs pre-rounded to tf32.
//   C[m,n] = sum_k A[m*lda+k] * B[n*ldb+k]
// 256 threads (8 warps, 2x4), block 128x128, warp tile 64x32 (4x4 m16n8k8).
// BK=16, 4 smem slots, per-stage mbarrier pipeline (R10 design, unchanged).
// NEW: fragment loads via ldmatrix.x4 (6 LDSM per k8 instead of 24 LDS.32);
//      stride-20 rows stay bank-conflict-free for ldmatrix (20r mod 32
//      partitions banks).
// NEW: sym!=0 => C symmetric (A==B, M==N==ldc): CTAs with bn<bm exit,
//      off-diagonal tiles also store the transposed tile.
// ---------------------------------------------------------------------------
#define STG_F 5120          // floats per stage (2*128*20)
#define NSTG  4
#define GEMM_SMEM (64 + NSTG * STG_F * 4)   // 64B barriers + 80KB stages

__device__ __forceinline__ void issue_stage(uint32_t dbase, int slot,
    const float* Ag, const float* Bg, int kbase, int lda, int ldb, int tid)
{
    const int r  = tid >> 1;            // 0..127
    const int c0 = (tid & 1) * 8;       // 0 or 8
    uint32_t a_off = dbase + (uint32_t)(slot * STG_F + r * 20 + c0) * 4u;
    uint32_t b_off = a_off + 2560u * 4u;
    const float* ap = Ag + (long)r * lda + kbase + c0;
    const float* bp = Bg + (long)r * ldb + kbase + c0;
    cp16(a_off,      ap);
    cp16(a_off + 16, ap + 4);
    cp16(b_off,      bp);
    cp16(b_off + 16, bp + 4);
}

__global__ __launch_bounds__(256, 2)
void gemm_tc(const float* __restrict__ A, const float* __restrict__ B,
             float* __restrict__ C,
             int K, int lda, int ldb, int ldc,
             long sA, long sB, long sC, int modB, int sym)
{
    const int bm = blockIdx.y * 128;
    const int bn = blockIdx.x * 128;
    if (sym && bn < bm) return;          // symmetric: upper triangle only

    extern __shared__ float sm[];
    const uint32_t sbase = smem_u32(sm);     // barriers: full[4] @0, empty[4] @32
    const uint32_t dbase = sbase + 64;       // stage data

    const int tid = threadIdx.x;
    const int batch = blockIdx.z;

    const float* Ag = A + (long)batch * sA + (long)bm * lda;
    const float* Bg = B + (long)(batch % modB) * sB + (long)bn * ldb;
    C += (long)batch * sC;

    const int wid  = tid >> 5;
    const int lane = tid & 31;
    const int wm = wid & 1;             // 0..1 (64 rows)
    const int wn = wid >> 1;            // 0..3 (32 cols)
    const int g = lane >> 2;            // 0..7
    const int t = lane & 3;             // 0..3

    // ldmatrix per-lane address components (row/col offsets within warp tile)
    const int a_ro = (lane & 7) + ((lane >> 3) & 1) * 8;   // 0..15
    const int a_co = (lane >> 4) * 4;                      // 0 or 4
    const int b_ro = (lane & 7) + (lane >> 4) * 8;         // 0..15
    const int b_co = ((lane >> 3) & 1) * 4;                // 0 or 4

    float acc[4][4][4];
    #pragma unroll
    for (int i = 0; i < 4; i++)
        #pragma unroll
        for (int j = 0; j < 4; j++)
            #pragma unroll
            for (int r = 0; r < 4; r++) acc[i][j][r] = 0.f;

    const int iters = K >> 4;           // BK = 16

    // init barriers, then CTA-wide sync once
    if (tid < NSTG) {
        MBAR_INIT(sbase + tid * 8, 256);        // full[tid]: all threads' cp.asyncs
        MBAR_INIT(sbase + 32 + tid * 8, 8);     // empty[tid]: one arrive per warp
    }
    __syncthreads();

    // prefill stages 0..2
    #pragma unroll
    for (int s = 0; s < 3; s++) {
        issue_stage(dbase, s, Ag, Bg, s * 16, lda, ldb, tid);
        cp_arrive(sbase + s * 8);
    }

    for (int it = 0; it < iters; ++it) {
        // 1) produce stage it+3
        const int pn = it + 3;
        if (pn < iters) {
            const int ps = pn & 3;
            if (pn >= NSTG)
                mbar_wait(sbase + 32 + ps * 8, ((pn >> 2) - 1) & 1);
            issue_stage(dbase, ps, Ag, Bg, pn * 16, lda, ldb, tid);
            cp_arrive(sbase + ps * 8);
        }

        // 2) wait for stage it
        const int slot = it & 3;
        mbar_wait(sbase + slot * 8, (it >> 2) & 1);

        const uint32_t aBase = dbase + (uint32_t)(slot * STG_F) * 4u;   // A [128][20]
        const uint32_t bBase = aBase + 2560u * 4u;                      // B [128][20]

        // 3) compute: 2 k-steps, frags via ldmatrix.x4
        #pragma unroll
        for (int ks = 0; ks < 2; ++ks) {
            const int k0 = ks * 8;
            unsigned af[4][4], bf[4][2];
            #pragma unroll
            for (int mt = 0; mt < 4; mt++) {
                uint32_t addr = aBase +
                    (uint32_t)(((wm * 64 + mt * 16 + a_ro) * 20) + k0 + a_co) * 4u;
                ldsm4(af[mt][0], af[mt][1], af[mt][2], af[mt][3], addr);
            }
            #pragma unroll
            for (int np = 0; np < 2; np++) {
                uint32_t addr = bBase +
                    (uint32_t)(((wn * 32 + np * 16 + b_ro) * 20) + k0 + b_co) * 4u;
                ldsm4(bf[2*np][0], bf[2*np][1], bf[2*np+1][0], bf[2*np+1][1], addr);
            }
            #pragma unroll
            for (int mt = 0; mt < 4; mt++)
                #pragma unroll
                for (int nt = 0; nt < 4; nt++)
                    mma_tf32(acc[mt][nt], af[mt], bf[nt]);
        }

        // 4) stage consumed -> warp-level release (lane 0; warp converged)
        if (lane == 0) mbar_arrive(sbase + 32 + slot * 8);
    }

    // epilogue
    #pragma unroll
    for (int mt = 0; mt < 4; mt++) {
        const int row = bm + wm * 64 + mt * 16 + g;
        #pragma unroll
        for (int nt = 0; nt < 4; nt++) {
            const int col = bn + wn * 32 + nt * 8 + 2 * t;
            float2 v0 = make_float2(acc[mt][nt][0], acc[mt][nt][1]);
            float2 v1 = make_float2(acc[mt][nt][2], acc[mt][nt][3]);
            *(float2*)(C + (long)row * ldc + col)       = v0;
            *(float2*)(C + (long)(row + 8) * ldc + col) = v1;
        }
    }
    if (sym && bm != bn) {
        // mirror tile: S[col][row] = S[row][col]
        #pragma unroll
        for (int mt = 0; mt < 4; mt++) {
            const int row = bm + wm * 64 + mt * 16 + g;
            #pragma unroll
            for (int nt = 0; nt < 4; nt++) {
                const int col = bn + wn * 32 + nt * 8 + 2 * t;
                C[(long)col * ldc + row]           = acc[mt][nt][0];
                C[(long)(col + 1) * ldc + row]     = acc[mt][nt][1];
                C[(long)col * ldc + row + 8]       = acc[mt][nt][2];
                C[(long)(col + 1) * ldc + row + 8] = acc[mt][nt][3];
            }
        }
    }
}

// ---------------------------------------------------------------------------
// Depthwise conv (kernel 3, pad 1 along last axis) + bias; output tf32-rounded
// ---------------------------------------------------------------------------
__global__ __launch_bounds__(256)
void conv_bias(const float* __restrict__ y, const float* __restrict__ wc,
               const float* __restrict__ bias, float* __restrict__ p)
{
    long idx = (long)blockIdx.x * blockDim.x + threadIdx.x;   // 8M elems
    if (idx >= (long)BC * NB * NB) return;
    int o = (int)(idx & (NB - 1));
    int c = (int)((idx >> 20) & 3);
    float w0 = wc[c*3+0], w1 = wc[c*3+1], w2 = wc[c*3+2];
    float mid = y[idx];
    float lft = (o > 0)      ? y[idx - 1] : 0.f;
    float rgt = (o < NB - 1) ? y[idx + 1] : 0.f;
    p[idx] = rtf(fmaf(lft, w0, fmaf(mid, w1, fmaf(rgt, w2, bias[c]))));
}

// ---------------------------------------------------------------------------
// RoPE + transpose: Q[bcn][s][d] from p[bc][n*128+d][s]; output tf32-rounded
// ---------------------------------------------------------------------------
__global__ __launch_bounds__(256)
void rope_build(const float* __restrict__ p, float* __restrict__ Q)
{
    long idx = (long)blockIdx.x * blockDim.x + threadIdx.x;   // 4M
    if (idx >= (long)BCN * 64 * NB) return;
    int s   = (int)(idx & (NB - 1));
    int j   = (int)((idx >> 10) & 63);
    int bcn = (int)(idx >> 16);
    int bc = bcn >> 3, n = bcn & 7;

    const float* src = p + ((long)bc * NB + n * HD) * NB + s;
    float*       dst = Q + (long)bcn * (NB * HD) + (long)s * HD;

    if (j < 32) {
        float t0 = src[(2*j + 0) * NB];
        float t1 = src[(2*j + 1) * NB];
        float invf = powf(10000.f, -(float)(2*j) / (float)ROT);
        float ang = (float)s * invf;
        float cs = cosf(ang), sn = sinf(ang);
        dst[2*j + 0] = rtf(t0 * cs - t1 * sn);
        dst[2*j + 1] = rtf(t1 * cs + t0 * sn);
    } else {
        int d = ROT + (j - 32) * 2;
        dst[d + 0] = src[(d + 0) * NB];
        dst[d + 1] = src[(d + 1) * NB];
    }
}

// ---------------------------------------------------------------------------
// Row softmax with scale (one block per row of 1024); output tf32-rounded
// ---------------------------------------------------------------------------
__global__ __launch_bounds__(256)
void softmax_rows(float* __restrict__ S, float scale)
{
    float* row = S + (long)blockIdx.x * NB;
    const int t = threadIdx.x;
    __shared__ float red[32];

    float v[4];
    float m = -1e30f;
    #pragma unroll
    for (int i = 0; i < 4; i++) {
        v[i] = row[t + i * 256] * scale;
        m = fmaxf(m, v[i]);
    }
    #pragma unroll
    for (int o = 16; o > 0; o >>= 1) m = fmaxf(m, __shfl_xor_sync(~0u, m, o));
    if ((t & 31) == 0) red[t >> 5] = m;
    __syncthreads();
    if (t < 32) {
        float x = red[t & 7];
        #pragma unroll
        for (int o = 4; o > 0; o >>= 1) x = fmaxf(x, __shfl_xor_sync(~0u, x, o));
        red[t] = x;
    }
    __syncthreads();
    m = red[0];

    float sum = 0.f;
    #pragma unroll
    for (int i = 0; i < 4; i++) { v[i] = __expf(v[i] - m); sum += v[i]; }
    #pragma unroll
    for (int o = 16; o > 0; o >>= 1) sum += __shfl_xor_sync(~0u, sum, o);
    __syncthreads();
    if ((t & 31) == 0) red[t >> 5] = sum;
    __syncthreads();
    if (t < 32) {
        float x = red[t & 7];
        #pragma unroll
        for (int o = 4; o > 0; o >>= 1) x += __shfl_xor_sync(~0u, x, o);
        red[t] = x;
    }
    __syncthreads();
    float inv = 1.f / red[0];
    #pragma unroll
    for (int i = 0; i < 4; i++) row[t + i * 256] = rtf(v[i] * inv);
}

// ---------------------------------------------------------------------------
// Merge heads: a_m[bc][n*128+d][s] = av[bcn][s][d]; output tf32-rounded
// ---------------------------------------------------------------------------
__global__ __launch_bounds__(256)
void merge_heads(const float* __restrict__ av, float* __restrict__ am)
{
    __shared__ float tile[32][33];
    int bcn = blockIdx.z;
    const float* src = av + (long)bcn * (NB * HD);
    float*       dst = am + (long)bcn * (NB * HD);
    int d0 = blockIdx.x * 32, s0 = blockIdx.y * 32;
    int tx = threadIdx.x, ty = threadIdx.y;
    #pragma unroll
    for (int i = 0; i < 32; i += 8)
        tile[ty + i][tx] = src[(long)(s0 + ty + i) * HD + d0 + tx];
    __syncthreads();
    #pragma unroll
    for (int i = 0; i < 32; i += 8)
        dst[(long)(d0 + ty + i) * NB + s0 + tx] = rtf(tile[tx][ty + i]);
}

// ---------------------------------------------------------------------------
// Launch
// ---------------------------------------------------------------------------
extern "C" void kernel_launch(void* const* d_in, const int* in_sizes, int n_in,
                              void* d_out, int out_size)
{
    const float* x      = (const float*)d_in[0];  // (2,4,1024,1024)
    const float* w_lin  = (const float*)d_in[1];  // (4,1024,1024)
    const float* w_conv = (const float*)d_in[2];  // (4,1,1,3)
    const float* b_conv = (const float*)d_in[3];  // (4,)
    const float* w_out  = (const float*)d_in[4];  // (4,1024,1024)
    float* out = (float*)d_out;

    float *y, *p, *q, *s, *av, *am, *xc, *wl, *wo;
    cudaGetSymbolAddress((void**)&y,  g_y);
    cudaGetSymbolAddress((void**)&p,  g_p);
    cudaGetSymbolAddress((void**)&q,  g_q);
    cudaGetSymbolAddress((void**)&s,  g_s);
    cudaGetSymbolAddress((void**)&av, g_av);
    cudaGetSymbolAddress((void**)&am, g_am);
    cudaGetSymbolAddress((void**)&xc, g_xc);
    cudaGetSymbolAddress((void**)&wl, g_wl);
    cudaGetSymbolAddress((void**)&wo, g_wo);

    cudaFuncSetAttribute(gemm_tc, cudaFuncAttributeMaxDynamicSharedMemorySize, GEMM_SMEM);

    const long MM = (long)NB * NB;          // 1048576
    const long QS = (long)NB * HD;          // 131072

    // 0) pre-round GEMM inputs to tf32
    cvt_tf32<<<(int)(BC * MM / 4 / 256), 256>>>(x, xc, (int)(BC * MM / 4));
    cvt_tf32<<<(int)(CH * MM / 4 / 256), 256>>>(w_lin, wl, (int)(CH * MM / 4));
    cvt_tf32<<<(int)(CH * MM / 4 / 256), 256>>>(w_out, wo, (int)(CH * MM / 4));

    // 1) proj GEMM: y[bc] = x[bc] @ w_lin[c]^T
    gemm_tc<<<dim3(8, 8, BC), 256, GEMM_SMEM>>>(xc, wl, y,
        NB, NB, NB, NB, MM, MM, MM, CH, 0);

    // 2) depthwise conv3 + bias (writes tf32 p)
    conv_bias<<<(int)((BC * MM + 255) / 256), 256>>>(y, w_conv, b_conv, p);

    // 3) RoPE -> Q (== K), tf32
    rope_build<<<(int)(((long)BCN * 64 * NB + 255) / 256), 256>>>(p, q);

    // 4) scores = Q @ Q^T: symmetric -> upper-triangle tiles only + mirror
    gemm_tc<<<dim3(8, 8, BCN), 256, GEMM_SMEM>>>(q, q, s,
        HD, HD, HD, NB, QS, QS, MM, BCN, 1);

    // 5) softmax rows, scale = 1/sqrt(1024), writes tf32 probs
    softmax_rows<<<BCN * NB, 256>>>(s, 1.0f / 32.0f);

    // 6) av = P @ V   (V^T is the p slice: stride 131072 per bcn, ldb=1024)
    gemm_tc<<<dim3(1, 8, BCN), 256, GEMM_SMEM>>>(s, p, av,
        NB, NB, NB, HD, MM, QS, QS, BCN, 0);

    // 7) merge heads (batched transpose), writes tf32 am
    merge_heads<<<dim3(4, 32, BCN), dim3(32, 8)>>>(av, am);

    // 8) out GEMM: out[bc] = am[bc] @ w_out[c]^T
    gemm_tc<<<dim3(8, 8, BC), 256, GEMM_SMEM>>>(am, wo, out,
        NB, NB, NB, NB, MM, MM, MM, CH, 0);
}